// round 4
// baseline (speedup 1.0000x reference)
#include <cuda_runtime.h>
#include <math.h>

#define NN    100000
#define IN_C  64
#define HID   128
#define OUT_C 64

// ---------------- scratch (device globals; no allocation allowed) ----------------
__device__ __align__(16) float g_deg[NN];
__device__ __align__(16) float g_agg1[(size_t)NN * IN_C];   // 25.6 MB
__device__ __align__(16) float g_h[(size_t)NN * HID];       // 51.2 MB
__device__ __align__(16) float g_agg2[(size_t)NN * HID];    // 51.2 MB
__device__ int g_is64;

// ---------------- dtype detect: int64 vs int32 edge_index ----------------
__global__ void detect_kernel(const void* __restrict__ ei) {
    if (blockIdx.x == 0 && threadIdx.x == 0) {
        const unsigned long long* p = (const unsigned long long*)ei;
        int is64 = 1;
#pragma unroll
        for (int i = 0; i < 8; i++)
            if ((p[i] >> 32) != 0ull) is64 = 0;   // nonzero high word => int32 data
        g_is64 = is64;
    }
}

// ---------------- zero scratch each launch ----------------
__global__ void zero_kernel() {
    size_t i = (size_t)blockIdx.x * blockDim.x + threadIdx.x;
    size_t stride = (size_t)gridDim.x * blockDim.x;
    float4 z = make_float4(0.f, 0.f, 0.f, 0.f);
    float4* d0 = (float4*)g_deg;
    float4* d1 = (float4*)g_agg1;
    float4* d2 = (float4*)g_agg2;
    for (size_t t = i; t < NN / 4; t += stride) d0[t] = z;
    for (size_t t = i; t < (size_t)NN * IN_C / 4; t += stride) d1[t] = z;
    for (size_t t = i; t < (size_t)NN * HID / 4; t += stride) d2[t] = z;
}

// ---------------- conv1 aggregation: 16 lanes per edge (64 ch) ----------------
__global__ __launch_bounds__(256) void conv1_agg_kernel(
    const float* __restrict__ x, const void* __restrict__ ei, int E)
{
    int tid = blockIdx.x * blockDim.x + threadIdx.x;
    int e = tid >> 4;
    if (e >= E) return;
    int sub = threadIdx.x & 15;
    int is64 = g_is64;
    int src = 0, dst = 0;
    if (sub == 0) {
        if (is64) {
            const long long* p = (const long long*)ei;
            src = (int)p[e]; dst = (int)p[(size_t)E + e];
        } else {
            const int* p = (const int*)ei;
            src = p[e]; dst = p[(size_t)E + e];
        }
    }
    src = __shfl_sync(0xffffffffu, src, 0, 16);
    dst = __shfl_sync(0xffffffffu, dst, 0, 16);

    float4 v = *(const float4*)(x + (size_t)src * IN_C + sub * 4);
    float* d = g_agg1 + (size_t)dst * IN_C + sub * 4;
    asm volatile("red.global.add.v4.f32 [%0], {%1,%2,%3,%4};"
                 :: "l"(d), "f"(v.x), "f"(v.y), "f"(v.z), "f"(v.w) : "memory");
    if (sub == 0) atomicAdd(&g_deg[dst], 1.0f);
}

// ---------------- conv2 aggregation: 32 lanes per edge (128 ch) ----------------
__global__ __launch_bounds__(256) void conv2_agg_kernel(
    const void* __restrict__ ei, int E)
{
    int tid = blockIdx.x * blockDim.x + threadIdx.x;
    int e = tid >> 5;
    if (e >= E) return;
    int ln = threadIdx.x & 31;
    int is64 = g_is64;
    int src = 0, dst = 0;
    if (ln == 0) {
        if (is64) {
            const long long* p = (const long long*)ei;
            src = (int)p[e]; dst = (int)p[(size_t)E + e];
        } else {
            const int* p = (const int*)ei;
            src = p[e]; dst = p[(size_t)E + e];
        }
    }
    src = __shfl_sync(0xffffffffu, src, 0);
    dst = __shfl_sync(0xffffffffu, dst, 0);

    float4 v = *(const float4*)(g_h + (size_t)src * HID + ln * 4);
    float* d = g_agg2 + (size_t)dst * HID + ln * 4;
    asm volatile("red.global.add.v4.f32 [%0], {%1,%2,%3,%4};"
                 :: "l"(d), "f"(v.x), "f"(v.y), "f"(v.z), "f"(v.w) : "memory");
}

// ---------------- conv1 update: h = relu(agg1/deg @ Wl1 + bl1 + x @ Wr1) ----------------
// 128 threads = 128 out channels; 4 nodes batched; weights L1-resident via LDG.
__global__ __launch_bounds__(128) void conv1_update_kernel(
    const float* __restrict__ x,
    const float* __restrict__ Wl, const float* __restrict__ bl,
    const float* __restrict__ Wr)
{
    int j = threadIdx.x;                 // out channel 0..127
    float b = __ldg(&bl[j]);
    for (int g = blockIdx.x; g < NN / 4; g += gridDim.x) {
        int base = g * 4;
        const float* ag = g_agg1 + (size_t)base * IN_C;
        const float* xr = x + (size_t)base * IN_C;
        float al0 = 0, al1 = 0, al2 = 0, al3 = 0;
        float ar0 = 0, ar1 = 0, ar2 = 0, ar3 = 0;
#pragma unroll
        for (int k = 0; k < IN_C; k += 4) {
            float wl0 = __ldg(&Wl[(k + 0) * HID + j]);
            float wl1 = __ldg(&Wl[(k + 1) * HID + j]);
            float wl2 = __ldg(&Wl[(k + 2) * HID + j]);
            float wl3 = __ldg(&Wl[(k + 3) * HID + j]);
            float wr0 = __ldg(&Wr[(k + 0) * HID + j]);
            float wr1 = __ldg(&Wr[(k + 1) * HID + j]);
            float wr2 = __ldg(&Wr[(k + 2) * HID + j]);
            float wr3 = __ldg(&Wr[(k + 3) * HID + j]);
            float4 a, xv;
            a = __ldg((const float4*)(ag + 0 * IN_C + k));
            xv = __ldg((const float4*)(xr + 0 * IN_C + k));
            al0 += a.x * wl0 + a.y * wl1 + a.z * wl2 + a.w * wl3;
            ar0 += xv.x * wr0 + xv.y * wr1 + xv.z * wr2 + xv.w * wr3;
            a = __ldg((const float4*)(ag + 1 * IN_C + k));
            xv = __ldg((const float4*)(xr + 1 * IN_C + k));
            al1 += a.x * wl0 + a.y * wl1 + a.z * wl2 + a.w * wl3;
            ar1 += xv.x * wr0 + xv.y * wr1 + xv.z * wr2 + xv.w * wr3;
            a = __ldg((const float4*)(ag + 2 * IN_C + k));
            xv = __ldg((const float4*)(xr + 2 * IN_C + k));
            al2 += a.x * wl0 + a.y * wl1 + a.z * wl2 + a.w * wl3;
            ar2 += xv.x * wr0 + xv.y * wr1 + xv.z * wr2 + xv.w * wr3;
            a = __ldg((const float4*)(ag + 3 * IN_C + k));
            xv = __ldg((const float4*)(xr + 3 * IN_C + k));
            al3 += a.x * wl0 + a.y * wl1 + a.z * wl2 + a.w * wl3;
            ar3 += xv.x * wr0 + xv.y * wr1 + xv.z * wr2 + xv.w * wr3;
        }
        float d0 = fmaxf(g_deg[base + 0], 1.f);
        float d1 = fmaxf(g_deg[base + 1], 1.f);
        float d2 = fmaxf(g_deg[base + 2], 1.f);
        float d3 = fmaxf(g_deg[base + 3], 1.f);
        g_h[(size_t)(base + 0) * HID + j] = fmaxf(al0 / d0 + b + ar0, 0.f);
        g_h[(size_t)(base + 1) * HID + j] = fmaxf(al1 / d1 + b + ar1, 0.f);
        g_h[(size_t)(base + 2) * HID + j] = fmaxf(al2 / d2 + b + ar2, 0.f);
        g_h[(size_t)(base + 3) * HID + j] = fmaxf(al3 / d3 + b + ar3, 0.f);
    }
}

// ---------------- conv2 update: emb = agg2/deg @ Wl2 + bl2 + h @ Wr2 ----------------
// 128 threads: threads 0..63 -> nodes 0..3, threads 64..127 -> nodes 4..7 (channel j&63)
__global__ __launch_bounds__(128) void conv2_update_kernel(
    const float* __restrict__ Wl, const float* __restrict__ bl,
    const float* __restrict__ Wr, float* __restrict__ emb)
{
    int j = threadIdx.x;
    int c = j & 63;
    int nb = (j >> 6) * 4;               // 0 or 4
    float b = __ldg(&bl[c]);
    for (int g = blockIdx.x; g < NN / 8; g += gridDim.x) {
        int base = g * 8;
        const float* ag = g_agg2 + (size_t)(base + nb) * HID;
        const float* hr = g_h + (size_t)(base + nb) * HID;
        float al0 = 0, al1 = 0, al2 = 0, al3 = 0;
        float ar0 = 0, ar1 = 0, ar2 = 0, ar3 = 0;
#pragma unroll 8
        for (int k = 0; k < HID; k += 4) {
            float wl0 = __ldg(&Wl[(k + 0) * OUT_C + c]);
            float wl1 = __ldg(&Wl[(k + 1) * OUT_C + c]);
            float wl2 = __ldg(&Wl[(k + 2) * OUT_C + c]);
            float wl3 = __ldg(&Wl[(k + 3) * OUT_C + c]);
            float wr0 = __ldg(&Wr[(k + 0) * OUT_C + c]);
            float wr1 = __ldg(&Wr[(k + 1) * OUT_C + c]);
            float wr2 = __ldg(&Wr[(k + 2) * OUT_C + c]);
            float wr3 = __ldg(&Wr[(k + 3) * OUT_C + c]);
            float4 a, hv;
            a = __ldg((const float4*)(ag + 0 * HID + k));
            hv = __ldg((const float4*)(hr + 0 * HID + k));
            al0 += a.x * wl0 + a.y * wl1 + a.z * wl2 + a.w * wl3;
            ar0 += hv.x * wr0 + hv.y * wr1 + hv.z * wr2 + hv.w * wr3;
            a = __ldg((const float4*)(ag + 1 * HID + k));
            hv = __ldg((const float4*)(hr + 1 * HID + k));
            al1 += a.x * wl0 + a.y * wl1 + a.z * wl2 + a.w * wl3;
            ar1 += hv.x * wr0 + hv.y * wr1 + hv.z * wr2 + hv.w * wr3;
            a = __ldg((const float4*)(ag + 2 * HID + k));
            hv = __ldg((const float4*)(hr + 2 * HID + k));
            al2 += a.x * wl0 + a.y * wl1 + a.z * wl2 + a.w * wl3;
            ar2 += hv.x * wr0 + hv.y * wr1 + hv.z * wr2 + hv.w * wr3;
            a = __ldg((const float4*)(ag + 3 * HID + k));
            hv = __ldg((const float4*)(hr + 3 * HID + k));
            al3 += a.x * wl0 + a.y * wl1 + a.z * wl2 + a.w * wl3;
            ar3 += hv.x * wr0 + hv.y * wr1 + hv.z * wr2 + hv.w * wr3;
        }
        float d0 = fmaxf(g_deg[base + nb + 0], 1.f);
        float d1 = fmaxf(g_deg[base + nb + 1], 1.f);
        float d2 = fmaxf(g_deg[base + nb + 2], 1.f);
        float d3 = fmaxf(g_deg[base + nb + 3], 1.f);
        emb[(size_t)(base + nb + 0) * OUT_C + c] = al0 / d0 + b + ar0;
        emb[(size_t)(base + nb + 1) * OUT_C + c] = al1 / d1 + b + ar1;
        emb[(size_t)(base + nb + 2) * OUT_C + c] = al2 / d2 + b + ar2;
        emb[(size_t)(base + nb + 3) * OUT_C + c] = al3 / d3 + b + ar3;
    }
}

// ---------------- classifier: sigmoid(relu(relu(emb@Wc1+b)@Wc2+b)@Wc3+b) ----------------
__global__ __launch_bounds__(128) void classifier_kernel(
    const float* __restrict__ emb,
    const float* __restrict__ Wc1, const float* __restrict__ bc1,
    const float* __restrict__ Wc2, const float* __restrict__ bc2,
    const float* __restrict__ Wc3, const float* __restrict__ bc3,
    float* __restrict__ probs)
{
    __shared__ __align__(16) float sc1[4 * HID];
    __shared__ float sred[8];
    int j = threadIdx.x;
    float b1 = __ldg(&bc1[j]);
    float b2 = (j < 64) ? __ldg(&bc2[j]) : 0.f;
    float w3v = (j < 64) ? __ldg(&Wc3[j]) : 0.f;
    float b3 = __ldg(&bc3[0]);
    for (int g = blockIdx.x; g < NN / 4; g += gridDim.x) {
        int base = g * 4;
        const float* er = emb + (size_t)base * OUT_C;
        float a0 = b1, a1 = b1, a2 = b1, a3 = b1;
#pragma unroll
        for (int k = 0; k < OUT_C; k += 4) {
            float w0 = __ldg(&Wc1[(k + 0) * HID + j]);
            float w1 = __ldg(&Wc1[(k + 1) * HID + j]);
            float w2 = __ldg(&Wc1[(k + 2) * HID + j]);
            float w3 = __ldg(&Wc1[(k + 3) * HID + j]);
            float4 e;
            e = __ldg((const float4*)(er + 0 * OUT_C + k));
            a0 += e.x * w0 + e.y * w1 + e.z * w2 + e.w * w3;
            e = __ldg((const float4*)(er + 1 * OUT_C + k));
            a1 += e.x * w0 + e.y * w1 + e.z * w2 + e.w * w3;
            e = __ldg((const float4*)(er + 2 * OUT_C + k));
            a2 += e.x * w0 + e.y * w1 + e.z * w2 + e.w * w3;
            e = __ldg((const float4*)(er + 3 * OUT_C + k));
            a3 += e.x * w0 + e.y * w1 + e.z * w2 + e.w * w3;
        }
        sc1[0 * HID + j] = fmaxf(a0, 0.f);
        sc1[1 * HID + j] = fmaxf(a1, 0.f);
        sc1[2 * HID + j] = fmaxf(a2, 0.f);
        sc1[3 * HID + j] = fmaxf(a3, 0.f);
        __syncthreads();
        if (j < 64) {
            float p0 = b2, p1 = b2, p2 = b2, p3 = b2;
#pragma unroll 8
            for (int k = 0; k < HID; k += 4) {
                float w0 = __ldg(&Wc2[(k + 0) * 64 + j]);
                float w1 = __ldg(&Wc2[(k + 1) * 64 + j]);
                float w2 = __ldg(&Wc2[(k + 2) * 64 + j]);
                float w3 = __ldg(&Wc2[(k + 3) * 64 + j]);
                float4 cc;
                cc = *(const float4*)(sc1 + 0 * HID + k);
                p0 += cc.x * w0 + cc.y * w1 + cc.z * w2 + cc.w * w3;
                cc = *(const float4*)(sc1 + 1 * HID + k);
                p1 += cc.x * w0 + cc.y * w1 + cc.z * w2 + cc.w * w3;
                cc = *(const float4*)(sc1 + 2 * HID + k);
                p2 += cc.x * w0 + cc.y * w1 + cc.z * w2 + cc.w * w3;
                cc = *(const float4*)(sc1 + 3 * HID + k);
                p3 += cc.x * w0 + cc.y * w1 + cc.z * w2 + cc.w * w3;
            }
            p0 = fmaxf(p0, 0.f) * w3v;
            p1 = fmaxf(p1, 0.f) * w3v;
            p2 = fmaxf(p2, 0.f) * w3v;
            p3 = fmaxf(p3, 0.f) * w3v;
#pragma unroll
            for (int off = 16; off; off >>= 1) {
                p0 += __shfl_xor_sync(0xffffffffu, p0, off);
                p1 += __shfl_xor_sync(0xffffffffu, p1, off);
                p2 += __shfl_xor_sync(0xffffffffu, p2, off);
                p3 += __shfl_xor_sync(0xffffffffu, p3, off);
            }
            if ((j & 31) == 0) {
                int w = j >> 5;
                sred[w * 4 + 0] = p0;
                sred[w * 4 + 1] = p1;
                sred[w * 4 + 2] = p2;
                sred[w * 4 + 3] = p3;
            }
        }
        __syncthreads();
        if (j < 4) {
            float v = sred[j] + sred[4 + j] + b3;
            probs[base + j] = 1.0f / (1.0f + expf(-v));
        }
        __syncthreads();
    }
}

// ---------------- launch ----------------
extern "C" void kernel_launch(void* const* d_in, const int* in_sizes, int n_in,
                              void* d_out, int out_size)
{
    const float* x   = (const float*)d_in[0];
    const void*  ei  = d_in[1];
    const float* Wl1 = (const float*)d_in[2];
    const float* bl1 = (const float*)d_in[3];
    const float* Wr1 = (const float*)d_in[4];
    const float* Wl2 = (const float*)d_in[5];
    const float* bl2 = (const float*)d_in[6];
    const float* Wr2 = (const float*)d_in[7];
    const float* Wc1 = (const float*)d_in[8];
    const float* bc1 = (const float*)d_in[9];
    const float* Wc2 = (const float*)d_in[10];
    const float* bc2 = (const float*)d_in[11];
    const float* Wc3 = (const float*)d_in[12];
    const float* bc3 = (const float*)d_in[13];
    int E = in_sizes[1] / 2;

    float* out   = (float*)d_out;
    float* emb   = out;                          // [NN, 64]
    float* probs = out + (size_t)NN * OUT_C;     // [NN, 1]

    detect_kernel<<<1, 32>>>(ei);
    zero_kernel<<<2048, 256>>>();
    conv1_agg_kernel<<<(E + 15) / 16, 256>>>(x, ei, E);
    conv1_update_kernel<<<592, 128>>>(x, Wl1, bl1, Wr1);
    conv2_agg_kernel<<<(E + 7) / 8, 256>>>(ei, E);
    conv2_update_kernel<<<592, 128>>>(Wl2, bl2, Wr2, emb);
    classifier_kernel<<<592, 128>>>(emb, Wc1, bc1, Wc2, bc2, Wc3, bc3, probs);
}